// round 15
// baseline (speedup 1.0000x reference)
#include <cuda_runtime.h>
#include <cuda_fp16.h>
#include <cstdint>

#define N_NODES 100000
#define N_EDGES 1600000
#define HID 128
#define NH4 (HID/4)
#define N_GRAPHS 512
#define N_CLASSES 64
#define BN_EPS 1e-5f
#define SCAN_NB 391   // ceil(N_NODES/256)

#define TILE_M 128
#define MMA_BLOCKS ((N_NODES + TILE_M - 1) / TILE_M)   // 782
#define APAD 136                                        // halves per smem row
#define SMEM_MMA_BYTES (2 * 128 * APAD * 2)             // A + B fp16 tiles = 69632
#define NPWA 4                                          // nodes per warp in agg

// ---------------- scratch (device globals; allocation-free) ----------------
__device__ __align__(16) unsigned g_hW2[N_NODES * 64]; // payload = dinv*h@W, half2/u32
__device__ __align__(16) unsigned g_z2 [N_NODES * 64]; // pre-BN conv output, fp16
__device__ __align__(16) unsigned g_h1 [N_NODES * 64]; // h1, fp16
__device__ __align__(16) unsigned g_h2 [N_NODES * 64]; // h2, fp16
__device__ float g_dinv[N_NODES];
__device__ int   g_cnt[N_NODES];
__device__ int   g_rowptr[N_NODES + 1]; // intra-block partial prefix (+ g_boff[i>>8])
__device__ int   g_cursor[N_NODES];
__device__ int   g_bsum[SCAN_NB];
__device__ int   g_boff[SCAN_NB];
__device__ int   g_esrc[N_EDGES];       // CSR-sorted source node per edge
__device__ float g_stats[3 * 2 * HID];
__device__ float g_psum[N_GRAPHS * HID];
__device__ unsigned g_pmax[N_GRAPHS * HID];
__device__ int   g_pcnt[N_GRAPHS];

// ---------------- warp-MMA helpers ----------------
__device__ __forceinline__ uint32_t smem_u32(const void* p) {
    uint32_t a;
    asm("{ .reg .u64 t; cvta.to.shared.u64 t, %1; cvt.u32.u64 %0, t; }" : "=r"(a) : "l"(p));
    return a;
}
__device__ __forceinline__ void ldsm_x4(uint32_t* r, uint32_t addr) {
    asm volatile("ldmatrix.sync.aligned.m8n8.x4.shared.b16 {%0,%1,%2,%3}, [%4];"
                 : "=r"(r[0]), "=r"(r[1]), "=r"(r[2]), "=r"(r[3]) : "r"(addr));
}
__device__ __forceinline__ void ldsm_x4_t(uint32_t* r, uint32_t addr) {
    asm volatile("ldmatrix.sync.aligned.m8n8.x4.trans.shared.b16 {%0,%1,%2,%3}, [%4];"
                 : "=r"(r[0]), "=r"(r[1]), "=r"(r[2]), "=r"(r[3]) : "r"(addr));
}
__device__ __forceinline__ void mma16816(float* c, const uint32_t* a, const uint32_t* b) {
    asm volatile(
        "mma.sync.aligned.m16n8k16.row.col.f32.f16.f16.f32 "
        "{%0,%1,%2,%3}, {%4,%5,%6,%7}, {%8,%9}, {%0,%1,%2,%3};"
        : "+f"(c[0]), "+f"(c[1]), "+f"(c[2]), "+f"(c[3])
        : "r"(a[0]), "r"(a[1]), "r"(a[2]), "r"(a[3]), "r"(b[0]), "r"(b[1]));
}
__device__ __forceinline__ float2 h2f(unsigned u) {
    return __half22float2(*(__half2*)&u);
}
__device__ __forceinline__ __half2 u2h(unsigned u) { return *(__half2*)&u; }

// ---------------- setup kernels ----------------

__global__ __launch_bounds__(256) void zero_kernel() {
    int i = blockIdx.x * blockDim.x + threadIdx.x;
    int stride = gridDim.x * blockDim.x;
    for (int j = i; j < N_NODES; j += stride) { g_cnt[j] = 0; g_cursor[j] = 0; }
    for (int j = i; j < 3 * 2 * HID; j += stride) g_stats[j] = 0.0f;
    for (int j = i; j < N_GRAPHS * HID; j += stride) { g_psum[j] = 0.0f; g_pmax[j] = 0u; }
    for (int j = i; j < N_GRAPHS; j += stride) g_pcnt[j] = 0;
}

__global__ __launch_bounds__(256) void hist_kernel(const int* __restrict__ dst) {
    int e = blockIdx.x * blockDim.x + threadIdx.x;
    if (e < N_EDGES) atomicAdd(&g_cnt[dst[e]], 1);
}

// per-block partial scan of g_cnt -> g_rowptr, block totals -> g_bsum, dinv folded in
__global__ __launch_bounds__(256) void scanA_kernel() {
    int t = threadIdx.x, b = blockIdx.x;
    int i = b * 256 + t;
    int v = (i < N_NODES) ? g_cnt[i] : 0;
    if (i < N_NODES) g_dinv[i] = rsqrtf((float)v + 1.0f);
    int x = v;
#pragma unroll
    for (int o = 1; o < 32; o <<= 1) {
        int y = __shfl_up_sync(0xffffffffu, x, o);
        if ((t & 31) >= o) x += y;
    }
    __shared__ int wsum[8];
    if ((t & 31) == 31) wsum[t >> 5] = x;
    __syncthreads();
    if (t < 32) {
        int s = (t < 8) ? wsum[t] : 0;
#pragma unroll
        for (int o = 1; o < 8; o <<= 1) {
            int y = __shfl_up_sync(0xffffffffu, s, o);
            if (t >= o) s += y;
        }
        if (t < 8) wsum[t] = s;
    }
    __syncthreads();
    int warpoff = (t >= 32) ? wsum[(t >> 5) - 1] : 0;
    int incl = x + warpoff;
    if (i < N_NODES) g_rowptr[i] = incl - v;
    if (t == 255) g_bsum[b] = incl;
}

__global__ __launch_bounds__(512) void scanB_kernel() {
    __shared__ int sh[512];
    int t = threadIdx.x;
    int v = (t < SCAN_NB) ? g_bsum[t] : 0;
    sh[t] = v;
    __syncthreads();
    for (int o = 1; o < 512; o <<= 1) {
        int y = (t >= o) ? sh[t - o] : 0;
        __syncthreads();
        sh[t] += y;
        __syncthreads();
    }
    if (t < SCAN_NB) g_boff[t] = sh[t] - v;
    if (t == SCAN_NB - 1) g_rowptr[N_NODES] = v;
}

__global__ __launch_bounds__(256) void scatter_kernel(const int* __restrict__ src,
                                                      const int* __restrict__ dst) {
    int e = blockIdx.x * blockDim.x + threadIdx.x;
    if (e >= N_EDGES) return;
    int d = dst[e];
    int pos = g_rowptr[d] + g_boff[d >> 8] + atomicAdd(&g_cursor[d], 1);
    g_esrc[pos] = src[e];
}

// ---------------- HMMA GEMM: payload = dinv * (A @ W) -> g_hW2 (fp16) ----------------
// mode 0: A = Aext (x fp32). mode 1: A = relu(bn(g_z2)), h -> g_h1.
// mode 2: A = relu(bn(g_z2) + g_h1), h -> g_h2.
__global__ __launch_bounds__(256, 3) void mma_kernel(const float* __restrict__ Aext,
                                                     const float* __restrict__ W,
                                                     const float* __restrict__ gam,
                                                     const float* __restrict__ bet,
                                                     int statIdx, int mode) {
    extern __shared__ __align__(16) __half smh[];
    __half* As = smh;                  // [128][APAD]
    __half* Bs = smh + 128 * APAD;     // [128][APAD]
    __shared__ __align__(16) float s_sc[HID];
    __shared__ __align__(16) float s_sh[HID];

    int tid = threadIdx.x;
    int lane = tid & 31, wid = tid >> 5;
    int rowBase = blockIdx.x * TILE_M;

    if (mode != 0) {
        if (tid < HID) {
            const float* st = &g_stats[statIdx * 2 * HID];
            const float invN = 1.0f / (float)N_NODES;
            float mu = st[tid] * invN;
            float var = st[HID + tid] * invN - mu * mu;
            float scv = gam[tid] * rsqrtf(var + BN_EPS);
            s_sc[tid] = scv;
            s_sh[tid] = bet[tid] - mu * scv;
        }
        __syncthreads();
    }

    // ---- stage A (fp16 path with BN fusion) and B = W ----
    {
        int r = tid >> 1;            // 0..127
        int hf = (tid & 1) * 64;     // half-row offset
        int row = rowBase + r;
        bool valid = row < N_NODES;
        unsigned* hout = (mode == 1) ? g_h1 : g_h2;
#pragma unroll
        for (int cc = 0; cc < 8; ++cc) {
            int c = hf + cc * 8;
            uint4 u = make_uint4(0, 0, 0, 0);
            if (valid) {
                if (mode == 0) {
                    float4 v0 = *(const float4*)&Aext[row * 128 + c];
                    float4 v1 = *(const float4*)&Aext[row * 128 + c + 4];
                    __half2 p0 = __floats2half2_rn(v0.x, v0.y);
                    __half2 p1 = __floats2half2_rn(v0.z, v0.w);
                    __half2 p2 = __floats2half2_rn(v1.x, v1.y);
                    __half2 p3 = __floats2half2_rn(v1.z, v1.w);
                    u.x = *(unsigned*)&p0; u.y = *(unsigned*)&p1;
                    u.z = *(unsigned*)&p2; u.w = *(unsigned*)&p3;
                } else {
                    uint4 zu = *(const uint4*)&g_z2[row * 64 + (c >> 1)];
                    float2 f0 = h2f(zu.x), f1 = h2f(zu.y), f2 = h2f(zu.z), f3 = h2f(zu.w);
                    float4 s0 = *(const float4*)&s_sc[c];
                    float4 s1 = *(const float4*)&s_sc[c + 4];
                    float4 h0 = *(const float4*)&s_sh[c];
                    float4 h1 = *(const float4*)&s_sh[c + 4];
                    f0.x = f0.x * s0.x + h0.x; f0.y = f0.y * s0.y + h0.y;
                    f1.x = f1.x * s0.z + h0.z; f1.y = f1.y * s0.w + h0.w;
                    f2.x = f2.x * s1.x + h1.x; f2.y = f2.y * s1.y + h1.y;
                    f3.x = f3.x * s1.z + h1.z; f3.y = f3.y * s1.w + h1.w;
                    if (mode == 2) {
                        uint4 ru = *(const uint4*)&g_h1[row * 64 + (c >> 1)];
                        float2 r0 = h2f(ru.x), r1 = h2f(ru.y), r2 = h2f(ru.z), r3 = h2f(ru.w);
                        f0.x += r0.x; f0.y += r0.y;
                        f1.x += r1.x; f1.y += r1.y;
                        f2.x += r2.x; f2.y += r2.y;
                        f3.x += r3.x; f3.y += r3.y;
                    }
                    f0.x = fmaxf(f0.x, 0.0f); f0.y = fmaxf(f0.y, 0.0f);
                    f1.x = fmaxf(f1.x, 0.0f); f1.y = fmaxf(f1.y, 0.0f);
                    f2.x = fmaxf(f2.x, 0.0f); f2.y = fmaxf(f2.y, 0.0f);
                    f3.x = fmaxf(f3.x, 0.0f); f3.y = fmaxf(f3.y, 0.0f);
                    __half2 p0 = __floats2half2_rn(f0.x, f0.y);
                    __half2 p1 = __floats2half2_rn(f1.x, f1.y);
                    __half2 p2 = __floats2half2_rn(f2.x, f2.y);
                    __half2 p3 = __floats2half2_rn(f3.x, f3.y);
                    u.x = *(unsigned*)&p0; u.y = *(unsigned*)&p1;
                    u.z = *(unsigned*)&p2; u.w = *(unsigned*)&p3;
                    *(uint4*)&hout[row * 64 + (c >> 1)] = u;
                }
            }
            *(uint4*)&As[r * APAD + c] = u;

            float4 w0 = *(const float4*)&W[r * 128 + c];
            float4 w1 = *(const float4*)&W[r * 128 + c + 4];
            __half2 q0 = __floats2half2_rn(w0.x, w0.y);
            __half2 q1 = __floats2half2_rn(w0.z, w0.w);
            __half2 q2 = __floats2half2_rn(w1.x, w1.y);
            __half2 q3 = __floats2half2_rn(w1.z, w1.w);
            uint4 uw;
            uw.x = *(unsigned*)&q0; uw.y = *(unsigned*)&q1;
            uw.z = *(unsigned*)&q2; uw.w = *(unsigned*)&q3;
            *(uint4*)&Bs[r * APAD + c] = uw;
        }
    }
    __syncthreads();

    // ---- warp tiles: 4x2 warps, each 32(m) x 64(n) ----
    int wm = wid & 3;
    int wn = wid >> 2;
    float acc[2][8][4];
#pragma unroll
    for (int mt = 0; mt < 2; ++mt)
#pragma unroll
        for (int nt = 0; nt < 8; ++nt)
#pragma unroll
            for (int j = 0; j < 4; ++j) acc[mt][nt][j] = 0.0f;

    uint32_t As_base = smem_u32(As);
    uint32_t Bs_base = smem_u32(Bs);
    int a_row = wm * 32 + (lane & 7) + ((lane >> 3) & 1) * 8;
    int a_col = (lane >> 4) * 8;
    int b_row = (lane & 7) + ((lane >> 3) & 1) * 8;
    int b_col = wn * 64 + (lane >> 4) * 8;

#pragma unroll
    for (int kc = 0; kc < 8; ++kc) {
        int k0 = kc * 16;
        uint32_t afr[2][4];
#pragma unroll
        for (int mt = 0; mt < 2; ++mt) {
            uint32_t addr = As_base + (uint32_t)(((a_row + mt * 16) * APAD) + k0 + a_col) * 2u;
            ldsm_x4(afr[mt], addr);
        }
        uint32_t bfr[8][2];
#pragma unroll
        for (int j = 0; j < 4; ++j) {
            uint32_t r[4];
            uint32_t addr = Bs_base + (uint32_t)(((b_row + k0) * APAD) + b_col + j * 16) * 2u;
            ldsm_x4_t(r, addr);
            bfr[2 * j][0] = r[0]; bfr[2 * j][1] = r[1];
            bfr[2 * j + 1][0] = r[2]; bfr[2 * j + 1][1] = r[3];
        }
#pragma unroll
        for (int mt = 0; mt < 2; ++mt)
#pragma unroll
            for (int nt = 0; nt < 8; ++nt)
                mma16816(acc[mt][nt], afr[mt], bfr[nt]);
    }

    // ---- epilogue: payload = dinv[row] * C, fp16 ----
#pragma unroll
    for (int mt = 0; mt < 2; ++mt) {
        int grow0 = rowBase + wm * 32 + mt * 16 + (lane >> 2);
        float d0 = (grow0 < N_NODES) ? g_dinv[grow0] : 0.0f;
        float d8 = (grow0 + 8 < N_NODES) ? g_dinv[grow0 + 8] : 0.0f;
#pragma unroll
        for (int nt = 0; nt < 8; ++nt) {
            int cidx = wn * 32 + nt * 4 + (lane & 3);
            if (grow0 < N_NODES) {
                __half2 p = __floats2half2_rn(d0 * acc[mt][nt][0], d0 * acc[mt][nt][1]);
                g_hW2[grow0 * 64 + cidx] = *(unsigned*)&p;
            }
            if (grow0 + 8 < N_NODES) {
                __half2 p = __floats2half2_rn(d8 * acc[mt][nt][2], d8 * acc[mt][nt][3]);
                g_hW2[(grow0 + 8) * 64 + cidx] = *(unsigned*)&p;
            }
        }
    }
}

// ---------------- aggregate (4 nodes/warp, MLP-4 fp16-tree gather) + BN stats ----------------
// z_i = dinv_i * (sum_e payload[src_e] + payload[i]) + b
__global__ __launch_bounds__(256) void agg_kernel(const float* __restrict__ b, int layer) {
    __shared__ float ss[8][HID];
    __shared__ float sq[8][HID];
    int w = (threadIdx.x >> 5);
    int lane = threadIdx.x & 31;
    int node0 = ((blockIdx.x * blockDim.x + threadIdx.x) >> 5) * NPWA;
    const uint2* hw = (const uint2*)g_hW2;
    float4 bb = ((const float4*)b)[lane];
    float4 statS = make_float4(0, 0, 0, 0);
    float4 statQ = make_float4(0, 0, 0, 0);
#pragma unroll 1
    for (int nn = 0; nn < NPWA; ++nn) {
        int node = node0 + nn;
        if (node >= N_NODES) break;
        float4 acc = make_float4(0, 0, 0, 0);
        int e0 = g_rowptr[node] + g_boff[node >> 8];
        int e1 = g_rowptr[node + 1] + g_boff[(node + 1) >> 8];
        int e = e0;
        int efull = e0 + ((e1 - e0) & ~3);
        for (; e < efull; e += 4) {
            int s0 = g_esrc[e];
            int s1 = g_esrc[e + 1];
            int s2 = g_esrc[e + 2];
            int s3 = g_esrc[e + 3];
            uint2 u0 = hw[s0 * 32 + lane];
            uint2 u1 = hw[s1 * 32 + lane];
            uint2 u2 = hw[s2 * 32 + lane];
            uint2 u3 = hw[s3 * 32 + lane];
            __half2 xs = __hadd2(__hadd2(u2h(u0.x), u2h(u1.x)),
                                 __hadd2(u2h(u2.x), u2h(u3.x)));
            __half2 ys = __hadd2(__hadd2(u2h(u0.y), u2h(u1.y)),
                                 __hadd2(u2h(u2.y), u2h(u3.y)));
            float2 fx = __half22float2(xs);
            float2 fy = __half22float2(ys);
            acc.x += fx.x; acc.y += fx.y;
            acc.z += fy.x; acc.w += fy.y;
        }
        for (; e < e1; ++e) {
            int s = g_esrc[e];
            uint2 u = hw[s * 32 + lane];
            float2 f;
            f = h2f(u.x); acc.x += f.x; acc.y += f.y;
            f = h2f(u.y); acc.z += f.x; acc.w += f.y;
        }
        // self term + scale + bias
        {
            uint2 u = hw[node * 32 + lane];
            float2 f0 = h2f(u.x), f1 = h2f(u.y);
            acc.x += f0.x; acc.y += f0.y; acc.z += f1.x; acc.w += f1.y;
        }
        float di = g_dinv[node];
        acc.x = di * acc.x + bb.x;
        acc.y = di * acc.y + bb.y;
        acc.z = di * acc.z + bb.z;
        acc.w = di * acc.w + bb.w;
        __half2 za = __floats2half2_rn(acc.x, acc.y);
        __half2 zb = __floats2half2_rn(acc.z, acc.w);
        uint2 zo;
        zo.x = *(unsigned*)&za; zo.y = *(unsigned*)&zb;
        ((uint2*)g_z2)[node * 32 + lane] = zo;
        statS.x += acc.x; statS.y += acc.y; statS.z += acc.z; statS.w += acc.w;
        statQ.x += acc.x * acc.x; statQ.y += acc.y * acc.y;
        statQ.z += acc.z * acc.z; statQ.w += acc.w * acc.w;
    }
    *(float4*)&ss[w][lane * 4] = statS;
    *(float4*)&sq[w][lane * 4] = statQ;
    __syncthreads();
    int t = threadIdx.x;
    int arr = t >> 7;
    int c = t & 127;
    const float* base = (arr == 0) ? &ss[0][0] : &sq[0][0];
    float total = 0.0f;
#pragma unroll
    for (int ww = 0; ww < 8; ++ww) total += base[ww * HID + c];
    atomicAdd(&g_stats[layer * 2 * HID + arr * HID + c], total);
}

__device__ __forceinline__ void pool_flush(int g, int lane, float4 s, float4 m, int cnt) {
    int base = g * HID + lane * 4;
    atomicAdd(&g_psum[base + 0], s.x);
    atomicAdd(&g_psum[base + 1], s.y);
    atomicAdd(&g_psum[base + 2], s.z);
    atomicAdd(&g_psum[base + 3], s.w);
    atomicMax(&g_pmax[base + 0], __float_as_uint(m.x));
    atomicMax(&g_pmax[base + 1], __float_as_uint(m.y));
    atomicMax(&g_pmax[base + 2], __float_as_uint(m.z));
    atomicMax(&g_pmax[base + 3], __float_as_uint(m.w));
    if (lane == 0) atomicAdd(&g_pcnt[g], cnt);
}

// pool with fused layer-3 BN + residual + relu (BN from g_stats[2]); fp16 inputs
__global__ __launch_bounds__(256) void pool_kernel(const int* __restrict__ batch,
                                                   const float* __restrict__ gam,
                                                   const float* __restrict__ bet) {
    __shared__ __align__(16) float s_sc[HID];
    __shared__ __align__(16) float s_sh[HID];
    {
        int t = threadIdx.x;
        if (t < HID) {
            const float* st = &g_stats[2 * 2 * HID];
            const float invN = 1.0f / (float)N_NODES;
            float mu = st[t] * invN;
            float var = st[HID + t] * invN - mu * mu;
            float scv = gam[t] * rsqrtf(var + BN_EPS);
            s_sc[t] = scv;
            s_sh[t] = bet[t] - mu * scv;
        }
        __syncthreads();
    }
    const int NPW = 16;
    int warp = (blockIdx.x * blockDim.x + threadIdx.x) >> 5;
    int lane = threadIdx.x & 31;
    int n0 = warp * NPW;
    if (n0 >= N_NODES) return;
    int n1 = min(n0 + NPW, N_NODES);
    const uint2* z2 = (const uint2*)g_z2;
    const uint2* r2 = (const uint2*)g_h2;
    float4 sc = *(const float4*)&s_sc[lane * 4];
    float4 sh = *(const float4*)&s_sh[lane * 4];
    float4 sacc = make_float4(0, 0, 0, 0);
    float4 macc = make_float4(0, 0, 0, 0);
    int cur = batch[n0];
    int cnt = 0;
    for (int n = n0; n < n1; ++n) {
        int g = batch[n];
        if (g != cur) {
            pool_flush(cur, lane, sacc, macc, cnt);
            sacc = make_float4(0, 0, 0, 0);
            macc = make_float4(0, 0, 0, 0);
            cnt = 0; cur = g;
        }
        uint2 zu = z2[n * 32 + lane];
        uint2 ru = r2[n * 32 + lane];
        float2 z0 = h2f(zu.x), z1 = h2f(zu.y);
        float2 r0 = h2f(ru.x), r1 = h2f(ru.y);
        float4 v;
        v.x = fmaxf(z0.x * sc.x + sh.x + r0.x, 0.0f);
        v.y = fmaxf(z0.y * sc.y + sh.y + r0.y, 0.0f);
        v.z = fmaxf(z1.x * sc.z + sh.z + r1.x, 0.0f);
        v.w = fmaxf(z1.y * sc.w + sh.w + r1.y, 0.0f);
        sacc.x += v.x; sacc.y += v.y; sacc.z += v.z; sacc.w += v.w;
        macc.x = fmaxf(macc.x, v.x); macc.y = fmaxf(macc.y, v.y);
        macc.z = fmaxf(macc.z, v.z); macc.w = fmaxf(macc.w, v.w);
        ++cnt;
    }
    pool_flush(cur, lane, sacc, macc, cnt);
}

__global__ __launch_bounds__(64) void head_kernel(const float* __restrict__ Wh,
                                                  const float* __restrict__ bh,
                                                  float* __restrict__ out) {
    int g = blockIdx.x;
    int c = threadIdx.x;
    float cntf = (float)g_pcnt[g];
    float inv = 1.0f / fmaxf(cntf, 1.0f);
    float acc = bh[c];
    for (int k = 0; k < HID; ++k) {
        float s = g_psum[g * HID + k];
        float m = s * inv;
        float mx = __uint_as_float(g_pmax[g * HID + k]);
        acc += m * Wh[k * N_CLASSES + c]
             + s * Wh[(HID + k) * N_CLASSES + c]
             + mx * Wh[(2 * HID + k) * N_CLASSES + c];
    }
    out[g * N_CLASSES + c] = acc;
}

// ---------------- launch ----------------
extern "C" void kernel_launch(void* const* d_in, const int* in_sizes, int n_in,
                              void* d_out, int out_size) {
    const float* x    = (const float*)d_in[0];
    const int*   ei   = (const int*)d_in[1];
    const int*   src  = ei;
    const int*   dst  = ei + N_EDGES;
    const int*   batch = (const int*)d_in[2];
    const float* W1 = (const float*)d_in[3];
    const float* b1 = (const float*)d_in[4];
    const float* g1 = (const float*)d_in[5];
    const float* be1 = (const float*)d_in[6];
    const float* W2 = (const float*)d_in[7];
    const float* b2 = (const float*)d_in[8];
    const float* g2 = (const float*)d_in[9];
    const float* be2 = (const float*)d_in[10];
    const float* W3 = (const float*)d_in[11];
    const float* b3 = (const float*)d_in[12];
    const float* g3 = (const float*)d_in[13];
    const float* be3 = (const float*)d_in[14];
    const float* Wh = (const float*)d_in[15];
    const float* bh = (const float*)d_in[16];
    float* out = (float*)d_out;

    cudaFuncSetAttribute(mma_kernel, cudaFuncAttributeMaxDynamicSharedMemorySize,
                         SMEM_MMA_BYTES);

    // one-time stream/event resources (created on first, non-captured, call)
    static cudaStream_t s1 = nullptr;
    static cudaEvent_t evFork = nullptr, evJoin = nullptr;
    if (s1 == nullptr) {
        cudaStreamCreateWithFlags(&s1, cudaStreamNonBlocking);
        cudaEventCreateWithFlags(&evFork, cudaEventDisableTiming);
        cudaEventCreateWithFlags(&evJoin, cudaEventDisableTiming);
    }

    const int TB = 256;
    const int edgeBlocks = (N_EDGES + TB - 1) / TB;
    const int aggBlocks = (N_NODES + 8 * NPWA - 1) / (8 * NPWA);
    const int poolWarps = (N_NODES + 15) / 16;
    const int poolBlocks = (poolWarps * 32 + TB - 1) / TB;

    zero_kernel<<<256, TB>>>();
    hist_kernel<<<edgeBlocks, TB>>>(dst);
    scanA_kernel<<<SCAN_NB, 256>>>();

    // fork: mma1 needs only x, W1, g_dinv (ready after scanA) — overlap with scanB+scatter
    cudaEventRecord(evFork, 0);
    cudaStreamWaitEvent(s1, evFork, 0);
    mma_kernel<<<MMA_BLOCKS, 256, SMEM_MMA_BYTES, s1>>>(x, W1, nullptr, nullptr, 0, 0);
    cudaEventRecord(evJoin, s1);

    scanB_kernel<<<1, 512>>>();
    scatter_kernel<<<edgeBlocks, TB>>>(src, dst);

    // join before agg1 (needs g_esrc from scatter AND g_hW2 from mma1)
    cudaStreamWaitEvent(0, evJoin, 0);
    agg_kernel<<<aggBlocks, TB>>>(b1, 0);

    // layer 2: A = h1 = relu(bn1(z1)), h1 -> g_h1
    mma_kernel<<<MMA_BLOCKS, 256, SMEM_MMA_BYTES>>>(nullptr, W2, g1, be1, 0, 1);
    agg_kernel<<<aggBlocks, TB>>>(b2, 1);

    // layer 3: A = h2 = relu(bn2(z2) + h1), h2 -> g_h2
    mma_kernel<<<MMA_BLOCKS, 256, SMEM_MMA_BYTES>>>(nullptr, W3, g2, be2, 1, 2);
    agg_kernel<<<aggBlocks, TB>>>(b3, 2);

    // pool (fused bn3 + residual h2) + head
    pool_kernel<<<poolBlocks, TB>>>(batch, g3, be3);
    head_kernel<<<N_GRAPHS, N_CLASSES>>>(Wh, bh, out);
}

// round 16
// speedup vs baseline: 1.1693x; 1.1693x over previous
#include <cuda_runtime.h>
#include <cuda_fp16.h>
#include <cstdint>

#define N_NODES 100000
#define N_EDGES 1600000
#define HID 128
#define NH4 (HID/4)
#define N_GRAPHS 512
#define N_CLASSES 64
#define BN_EPS 1e-5f
#define SCAN_NB 391   // ceil(N_NODES/256)

#define TILE_M 128
#define MMA_BLOCKS ((N_NODES + TILE_M - 1) / TILE_M)   // 782
#define APAD 136                                        // halves per smem row
#define SMEM_MMA_BYTES (2 * 128 * APAD * 2)             // A + B fp16 tiles = 69632
#define NPWA 4                                          // nodes per warp in agg

// ---------------- scratch (device globals; allocation-free) ----------------
__device__ __align__(16) unsigned g_hW2[N_NODES * 64]; // payload = dinv*h@W, half2/u32
__device__ __align__(16) unsigned g_z2 [N_NODES * 64]; // pre-BN conv output, fp16
__device__ __align__(16) unsigned g_h1 [N_NODES * 64]; // h1, fp16
__device__ __align__(16) unsigned g_h2 [N_NODES * 64]; // h2, fp16
__device__ float g_dinv[N_NODES];
__device__ int   g_cnt[N_NODES];
__device__ int   g_rowptr[N_NODES + 1]; // intra-block partial prefix (+ g_boff[i>>8])
__device__ int   g_cursor[N_NODES];
__device__ int   g_bsum[SCAN_NB];
__device__ int   g_boff[SCAN_NB];
__device__ int   g_esrc[N_EDGES];       // CSR-sorted source node per edge
__device__ float g_stats[3 * 2 * HID];
__device__ float g_psum[N_GRAPHS * HID];
__device__ unsigned g_pmax[N_GRAPHS * HID];
__device__ int   g_pcnt[N_GRAPHS];

// ---------------- warp-MMA helpers ----------------
__device__ __forceinline__ uint32_t smem_u32(const void* p) {
    uint32_t a;
    asm("{ .reg .u64 t; cvta.to.shared.u64 t, %1; cvt.u32.u64 %0, t; }" : "=r"(a) : "l"(p));
    return a;
}
__device__ __forceinline__ void ldsm_x4(uint32_t* r, uint32_t addr) {
    asm volatile("ldmatrix.sync.aligned.m8n8.x4.shared.b16 {%0,%1,%2,%3}, [%4];"
                 : "=r"(r[0]), "=r"(r[1]), "=r"(r[2]), "=r"(r[3]) : "r"(addr));
}
__device__ __forceinline__ void ldsm_x4_t(uint32_t* r, uint32_t addr) {
    asm volatile("ldmatrix.sync.aligned.m8n8.x4.trans.shared.b16 {%0,%1,%2,%3}, [%4];"
                 : "=r"(r[0]), "=r"(r[1]), "=r"(r[2]), "=r"(r[3]) : "r"(addr));
}
__device__ __forceinline__ void mma16816(float* c, const uint32_t* a, const uint32_t* b) {
    asm volatile(
        "mma.sync.aligned.m16n8k16.row.col.f32.f16.f16.f32 "
        "{%0,%1,%2,%3}, {%4,%5,%6,%7}, {%8,%9}, {%0,%1,%2,%3};"
        : "+f"(c[0]), "+f"(c[1]), "+f"(c[2]), "+f"(c[3])
        : "r"(a[0]), "r"(a[1]), "r"(a[2]), "r"(a[3]), "r"(b[0]), "r"(b[1]));
}
__device__ __forceinline__ float2 h2f(unsigned u) {
    return __half22float2(*(__half2*)&u);
}
__device__ __forceinline__ __half2 u2h(unsigned u) { return *(__half2*)&u; }

// ---------------- setup kernels ----------------

// critical path: only what hist/scan need
__global__ __launch_bounds__(256) void zero_cnt_kernel() {
    int i = blockIdx.x * blockDim.x + threadIdx.x;
    int stride = gridDim.x * blockDim.x;
    for (int j = i; j < N_NODES; j += stride) { g_cnt[j] = 0; g_cursor[j] = 0; }
}

// off critical path: stats/pool accumulators (side stream, joins before agg1)
__global__ __launch_bounds__(256) void zero_rest_kernel() {
    int i = blockIdx.x * blockDim.x + threadIdx.x;
    int stride = gridDim.x * blockDim.x;
    for (int j = i; j < 3 * 2 * HID; j += stride) g_stats[j] = 0.0f;
    for (int j = i; j < N_GRAPHS * HID; j += stride) { g_psum[j] = 0.0f; g_pmax[j] = 0u; }
    for (int j = i; j < N_GRAPHS; j += stride) g_pcnt[j] = 0;
}

__global__ __launch_bounds__(256) void hist_kernel(const int* __restrict__ dst) {
    int e = blockIdx.x * blockDim.x + threadIdx.x;
    if (e < N_EDGES) atomicAdd(&g_cnt[dst[e]], 1);
}

// per-block partial scan of g_cnt -> g_rowptr, block totals -> g_bsum, dinv folded in
__global__ __launch_bounds__(256) void scanA_kernel() {
    int t = threadIdx.x, b = blockIdx.x;
    int i = b * 256 + t;
    int v = (i < N_NODES) ? g_cnt[i] : 0;
    if (i < N_NODES) g_dinv[i] = rsqrtf((float)v + 1.0f);
    int x = v;
#pragma unroll
    for (int o = 1; o < 32; o <<= 1) {
        int y = __shfl_up_sync(0xffffffffu, x, o);
        if ((t & 31) >= o) x += y;
    }
    __shared__ int wsum[8];
    if ((t & 31) == 31) wsum[t >> 5] = x;
    __syncthreads();
    if (t < 32) {
        int s = (t < 8) ? wsum[t] : 0;
#pragma unroll
        for (int o = 1; o < 8; o <<= 1) {
            int y = __shfl_up_sync(0xffffffffu, s, o);
            if (t >= o) s += y;
        }
        if (t < 8) wsum[t] = s;
    }
    __syncthreads();
    int warpoff = (t >= 32) ? wsum[(t >> 5) - 1] : 0;
    int incl = x + warpoff;
    if (i < N_NODES) g_rowptr[i] = incl - v;
    if (t == 255) g_bsum[b] = incl;
}

__global__ __launch_bounds__(512) void scanB_kernel() {
    __shared__ int sh[512];
    int t = threadIdx.x;
    int v = (t < SCAN_NB) ? g_bsum[t] : 0;
    sh[t] = v;
    __syncthreads();
    for (int o = 1; o < 512; o <<= 1) {
        int y = (t >= o) ? sh[t - o] : 0;
        __syncthreads();
        sh[t] += y;
        __syncthreads();
    }
    if (t < SCAN_NB) g_boff[t] = sh[t] - v;
    if (t == SCAN_NB - 1) g_rowptr[N_NODES] = v;
}

__global__ __launch_bounds__(256) void scatter_kernel(const int* __restrict__ src,
                                                      const int* __restrict__ dst) {
    int e = blockIdx.x * blockDim.x + threadIdx.x;
    if (e >= N_EDGES) return;
    int d = dst[e];
    int pos = g_rowptr[d] + g_boff[d >> 8] + atomicAdd(&g_cursor[d], 1);
    g_esrc[pos] = src[e];
}

// ---------------- HMMA GEMM: payload = dinv * (A @ W) -> g_hW2 (fp16) ----------------
// mode 0: A = Aext (x fp32). mode 1: A = relu(bn(g_z2)), h -> g_h1.
// mode 2: A = relu(bn(g_z2) + g_h1), h -> g_h2.
__global__ __launch_bounds__(256) void mma_kernel(const float* __restrict__ Aext,
                                                  const float* __restrict__ W,
                                                  const float* __restrict__ gam,
                                                  const float* __restrict__ bet,
                                                  int statIdx, int mode) {
    extern __shared__ __align__(16) __half smh[];
    __half* As = smh;                  // [128][APAD]
    __half* Bs = smh + 128 * APAD;     // [128][APAD]
    __shared__ __align__(16) float s_sc[HID];
    __shared__ __align__(16) float s_sh[HID];

    int tid = threadIdx.x;
    int lane = tid & 31, wid = tid >> 5;
    int rowBase = blockIdx.x * TILE_M;

    if (mode != 0) {
        if (tid < HID) {
            const float* st = &g_stats[statIdx * 2 * HID];
            const float invN = 1.0f / (float)N_NODES;
            float mu = st[tid] * invN;
            float var = st[HID + tid] * invN - mu * mu;
            float scv = gam[tid] * rsqrtf(var + BN_EPS);
            s_sc[tid] = scv;
            s_sh[tid] = bet[tid] - mu * scv;
        }
        __syncthreads();
    }

    // ---- stage A (fp16 path with BN fusion) and B = W ----
    {
        int r = tid >> 1;            // 0..127
        int hf = (tid & 1) * 64;     // half-row offset
        int row = rowBase + r;
        bool valid = row < N_NODES;
        unsigned* hout = (mode == 1) ? g_h1 : g_h2;
#pragma unroll
        for (int cc = 0; cc < 8; ++cc) {
            int c = hf + cc * 8;
            uint4 u = make_uint4(0, 0, 0, 0);
            if (valid) {
                if (mode == 0) {
                    float4 v0 = *(const float4*)&Aext[row * 128 + c];
                    float4 v1 = *(const float4*)&Aext[row * 128 + c + 4];
                    __half2 p0 = __floats2half2_rn(v0.x, v0.y);
                    __half2 p1 = __floats2half2_rn(v0.z, v0.w);
                    __half2 p2 = __floats2half2_rn(v1.x, v1.y);
                    __half2 p3 = __floats2half2_rn(v1.z, v1.w);
                    u.x = *(unsigned*)&p0; u.y = *(unsigned*)&p1;
                    u.z = *(unsigned*)&p2; u.w = *(unsigned*)&p3;
                } else {
                    uint4 zu = *(const uint4*)&g_z2[row * 64 + (c >> 1)];
                    float2 f0 = h2f(zu.x), f1 = h2f(zu.y), f2 = h2f(zu.z), f3 = h2f(zu.w);
                    float4 s0 = *(const float4*)&s_sc[c];
                    float4 s1 = *(const float4*)&s_sc[c + 4];
                    float4 h0 = *(const float4*)&s_sh[c];
                    float4 h1 = *(const float4*)&s_sh[c + 4];
                    f0.x = f0.x * s0.x + h0.x; f0.y = f0.y * s0.y + h0.y;
                    f1.x = f1.x * s0.z + h0.z; f1.y = f1.y * s0.w + h0.w;
                    f2.x = f2.x * s1.x + h1.x; f2.y = f2.y * s1.y + h1.y;
                    f3.x = f3.x * s1.z + h1.z; f3.y = f3.y * s1.w + h1.w;
                    if (mode == 2) {
                        uint4 ru = *(const uint4*)&g_h1[row * 64 + (c >> 1)];
                        float2 r0 = h2f(ru.x), r1 = h2f(ru.y), r2 = h2f(ru.z), r3 = h2f(ru.w);
                        f0.x += r0.x; f0.y += r0.y;
                        f1.x += r1.x; f1.y += r1.y;
                        f2.x += r2.x; f2.y += r2.y;
                        f3.x += r3.x; f3.y += r3.y;
                    }
                    f0.x = fmaxf(f0.x, 0.0f); f0.y = fmaxf(f0.y, 0.0f);
                    f1.x = fmaxf(f1.x, 0.0f); f1.y = fmaxf(f1.y, 0.0f);
                    f2.x = fmaxf(f2.x, 0.0f); f2.y = fmaxf(f2.y, 0.0f);
                    f3.x = fmaxf(f3.x, 0.0f); f3.y = fmaxf(f3.y, 0.0f);
                    __half2 p0 = __floats2half2_rn(f0.x, f0.y);
                    __half2 p1 = __floats2half2_rn(f1.x, f1.y);
                    __half2 p2 = __floats2half2_rn(f2.x, f2.y);
                    __half2 p3 = __floats2half2_rn(f3.x, f3.y);
                    u.x = *(unsigned*)&p0; u.y = *(unsigned*)&p1;
                    u.z = *(unsigned*)&p2; u.w = *(unsigned*)&p3;
                    *(uint4*)&hout[row * 64 + (c >> 1)] = u;
                }
            }
            *(uint4*)&As[r * APAD + c] = u;

            float4 w0 = *(const float4*)&W[r * 128 + c];
            float4 w1 = *(const float4*)&W[r * 128 + c + 4];
            __half2 q0 = __floats2half2_rn(w0.x, w0.y);
            __half2 q1 = __floats2half2_rn(w0.z, w0.w);
            __half2 q2 = __floats2half2_rn(w1.x, w1.y);
            __half2 q3 = __floats2half2_rn(w1.z, w1.w);
            uint4 uw;
            uw.x = *(unsigned*)&q0; uw.y = *(unsigned*)&q1;
            uw.z = *(unsigned*)&q2; uw.w = *(unsigned*)&q3;
            *(uint4*)&Bs[r * APAD + c] = uw;
        }
    }
    __syncthreads();

    // ---- warp tiles: 4x2 warps, each 32(m) x 64(n) ----
    int wm = wid & 3;
    int wn = wid >> 2;
    float acc[2][8][4];
#pragma unroll
    for (int mt = 0; mt < 2; ++mt)
#pragma unroll
        for (int nt = 0; nt < 8; ++nt)
#pragma unroll
            for (int j = 0; j < 4; ++j) acc[mt][nt][j] = 0.0f;

    uint32_t As_base = smem_u32(As);
    uint32_t Bs_base = smem_u32(Bs);
    int a_row = wm * 32 + (lane & 7) + ((lane >> 3) & 1) * 8;
    int a_col = (lane >> 4) * 8;
    int b_row = (lane & 7) + ((lane >> 3) & 1) * 8;
    int b_col = wn * 64 + (lane >> 4) * 8;

#pragma unroll
    for (int kc = 0; kc < 8; ++kc) {
        int k0 = kc * 16;
        uint32_t afr[2][4];
#pragma unroll
        for (int mt = 0; mt < 2; ++mt) {
            uint32_t addr = As_base + (uint32_t)(((a_row + mt * 16) * APAD) + k0 + a_col) * 2u;
            ldsm_x4(afr[mt], addr);
        }
        uint32_t bfr[8][2];
#pragma unroll
        for (int j = 0; j < 4; ++j) {
            uint32_t r[4];
            uint32_t addr = Bs_base + (uint32_t)(((b_row + k0) * APAD) + b_col + j * 16) * 2u;
            ldsm_x4_t(r, addr);
            bfr[2 * j][0] = r[0]; bfr[2 * j][1] = r[1];
            bfr[2 * j + 1][0] = r[2]; bfr[2 * j + 1][1] = r[3];
        }
#pragma unroll
        for (int mt = 0; mt < 2; ++mt)
#pragma unroll
            for (int nt = 0; nt < 8; ++nt)
                mma16816(acc[mt][nt], afr[mt], bfr[nt]);
    }

    // ---- epilogue: payload = dinv[row] * C, fp16 ----
#pragma unroll
    for (int mt = 0; mt < 2; ++mt) {
        int grow0 = rowBase + wm * 32 + mt * 16 + (lane >> 2);
        float d0 = (grow0 < N_NODES) ? g_dinv[grow0] : 0.0f;
        float d8 = (grow0 + 8 < N_NODES) ? g_dinv[grow0 + 8] : 0.0f;
#pragma unroll
        for (int nt = 0; nt < 8; ++nt) {
            int cidx = wn * 32 + nt * 4 + (lane & 3);
            if (grow0 < N_NODES) {
                __half2 p = __floats2half2_rn(d0 * acc[mt][nt][0], d0 * acc[mt][nt][1]);
                g_hW2[grow0 * 64 + cidx] = *(unsigned*)&p;
            }
            if (grow0 + 8 < N_NODES) {
                __half2 p = __floats2half2_rn(d8 * acc[mt][nt][2], d8 * acc[mt][nt][3]);
                g_hW2[(grow0 + 8) * 64 + cidx] = *(unsigned*)&p;
            }
        }
    }
}

// ---------------- aggregate (4 nodes/warp, MLP-4 fp16-tree gather) + BN stats ----------------
// z_i = dinv_i * (sum_e payload[src_e] + payload[i]) + b
__global__ __launch_bounds__(256) void agg_kernel(const float* __restrict__ b, int layer) {
    __shared__ float ss[8][HID];
    __shared__ float sq[8][HID];
    int w = (threadIdx.x >> 5);
    int lane = threadIdx.x & 31;
    int node0 = ((blockIdx.x * blockDim.x + threadIdx.x) >> 5) * NPWA;
    const uint2* hw = (const uint2*)g_hW2;
    float4 bb = ((const float4*)b)[lane];
    float4 statS = make_float4(0, 0, 0, 0);
    float4 statQ = make_float4(0, 0, 0, 0);
#pragma unroll 1
    for (int nn = 0; nn < NPWA; ++nn) {
        int node = node0 + nn;
        if (node >= N_NODES) break;
        float4 acc = make_float4(0, 0, 0, 0);
        int e0 = g_rowptr[node] + g_boff[node >> 8];
        int e1 = g_rowptr[node + 1] + g_boff[(node + 1) >> 8];
        int e = e0;
        int efull = e0 + ((e1 - e0) & ~3);
        for (; e < efull; e += 4) {
            int s0 = g_esrc[e];
            int s1 = g_esrc[e + 1];
            int s2 = g_esrc[e + 2];
            int s3 = g_esrc[e + 3];
            uint2 u0 = hw[s0 * 32 + lane];
            uint2 u1 = hw[s1 * 32 + lane];
            uint2 u2 = hw[s2 * 32 + lane];
            uint2 u3 = hw[s3 * 32 + lane];
            __half2 xs = __hadd2(__hadd2(u2h(u0.x), u2h(u1.x)),
                                 __hadd2(u2h(u2.x), u2h(u3.x)));
            __half2 ys = __hadd2(__hadd2(u2h(u0.y), u2h(u1.y)),
                                 __hadd2(u2h(u2.y), u2h(u3.y)));
            float2 fx = __half22float2(xs);
            float2 fy = __half22float2(ys);
            acc.x += fx.x; acc.y += fx.y;
            acc.z += fy.x; acc.w += fy.y;
        }
        for (; e < e1; ++e) {
            int s = g_esrc[e];
            uint2 u = hw[s * 32 + lane];
            float2 f;
            f = h2f(u.x); acc.x += f.x; acc.y += f.y;
            f = h2f(u.y); acc.z += f.x; acc.w += f.y;
        }
        // self term + scale + bias
        {
            uint2 u = hw[node * 32 + lane];
            float2 f0 = h2f(u.x), f1 = h2f(u.y);
            acc.x += f0.x; acc.y += f0.y; acc.z += f1.x; acc.w += f1.y;
        }
        float di = g_dinv[node];
        acc.x = di * acc.x + bb.x;
        acc.y = di * acc.y + bb.y;
        acc.z = di * acc.z + bb.z;
        acc.w = di * acc.w + bb.w;
        __half2 za = __floats2half2_rn(acc.x, acc.y);
        __half2 zb = __floats2half2_rn(acc.z, acc.w);
        uint2 zo;
        zo.x = *(unsigned*)&za; zo.y = *(unsigned*)&zb;
        ((uint2*)g_z2)[node * 32 + lane] = zo;
        statS.x += acc.x; statS.y += acc.y; statS.z += acc.z; statS.w += acc.w;
        statQ.x += acc.x * acc.x; statQ.y += acc.y * acc.y;
        statQ.z += acc.z * acc.z; statQ.w += acc.w * acc.w;
    }
    *(float4*)&ss[w][lane * 4] = statS;
    *(float4*)&sq[w][lane * 4] = statQ;
    __syncthreads();
    int t = threadIdx.x;
    int arr = t >> 7;
    int c = t & 127;
    const float* base = (arr == 0) ? &ss[0][0] : &sq[0][0];
    float total = 0.0f;
#pragma unroll
    for (int ww = 0; ww < 8; ++ww) total += base[ww * HID + c];
    atomicAdd(&g_stats[layer * 2 * HID + arr * HID + c], total);
}

__device__ __forceinline__ void pool_flush(int g, int lane, float4 s, float4 m, int cnt) {
    int base = g * HID + lane * 4;
    atomicAdd(&g_psum[base + 0], s.x);
    atomicAdd(&g_psum[base + 1], s.y);
    atomicAdd(&g_psum[base + 2], s.z);
    atomicAdd(&g_psum[base + 3], s.w);
    atomicMax(&g_pmax[base + 0], __float_as_uint(m.x));
    atomicMax(&g_pmax[base + 1], __float_as_uint(m.y));
    atomicMax(&g_pmax[base + 2], __float_as_uint(m.z));
    atomicMax(&g_pmax[base + 3], __float_as_uint(m.w));
    if (lane == 0) atomicAdd(&g_pcnt[g], cnt);
}

// pool with fused layer-3 BN + residual + relu (BN from g_stats[2]); fp16 inputs
__global__ __launch_bounds__(256) void pool_kernel(const int* __restrict__ batch,
                                                   const float* __restrict__ gam,
                                                   const float* __restrict__ bet) {
    __shared__ __align__(16) float s_sc[HID];
    __shared__ __align__(16) float s_sh[HID];
    {
        int t = threadIdx.x;
        if (t < HID) {
            const float* st = &g_stats[2 * 2 * HID];
            const float invN = 1.0f / (float)N_NODES;
            float mu = st[t] * invN;
            float var = st[HID + t] * invN - mu * mu;
            float scv = gam[t] * rsqrtf(var + BN_EPS);
            s_sc[t] = scv;
            s_sh[t] = bet[t] - mu * scv;
        }
        __syncthreads();
    }
    const int NPW = 16;
    int warp = (blockIdx.x * blockDim.x + threadIdx.x) >> 5;
    int lane = threadIdx.x & 31;
    int n0 = warp * NPW;
    if (n0 >= N_NODES) return;
    int n1 = min(n0 + NPW, N_NODES);
    const uint2* z2 = (const uint2*)g_z2;
    const uint2* r2 = (const uint2*)g_h2;
    float4 sc = *(const float4*)&s_sc[lane * 4];
    float4 sh = *(const float4*)&s_sh[lane * 4];
    float4 sacc = make_float4(0, 0, 0, 0);
    float4 macc = make_float4(0, 0, 0, 0);
    int cur = batch[n0];
    int cnt = 0;
    for (int n = n0; n < n1; ++n) {
        int g = batch[n];
        if (g != cur) {
            pool_flush(cur, lane, sacc, macc, cnt);
            sacc = make_float4(0, 0, 0, 0);
            macc = make_float4(0, 0, 0, 0);
            cnt = 0; cur = g;
        }
        uint2 zu = z2[n * 32 + lane];
        uint2 ru = r2[n * 32 + lane];
        float2 z0 = h2f(zu.x), z1 = h2f(zu.y);
        float2 r0 = h2f(ru.x), r1 = h2f(ru.y);
        float4 v;
        v.x = fmaxf(z0.x * sc.x + sh.x + r0.x, 0.0f);
        v.y = fmaxf(z0.y * sc.y + sh.y + r0.y, 0.0f);
        v.z = fmaxf(z1.x * sc.z + sh.z + r1.x, 0.0f);
        v.w = fmaxf(z1.y * sc.w + sh.w + r1.y, 0.0f);
        sacc.x += v.x; sacc.y += v.y; sacc.z += v.z; sacc.w += v.w;
        macc.x = fmaxf(macc.x, v.x); macc.y = fmaxf(macc.y, v.y);
        macc.z = fmaxf(macc.z, v.z); macc.w = fmaxf(macc.w, v.w);
        ++cnt;
    }
    pool_flush(cur, lane, sacc, macc, cnt);
}

__global__ __launch_bounds__(64) void head_kernel(const float* __restrict__ Wh,
                                                  const float* __restrict__ bh,
                                                  float* __restrict__ out) {
    int g = blockIdx.x;
    int c = threadIdx.x;
    float cntf = (float)g_pcnt[g];
    float inv = 1.0f / fmaxf(cntf, 1.0f);
    float acc = bh[c];
    for (int k = 0; k < HID; ++k) {
        float s = g_psum[g * HID + k];
        float m = s * inv;
        float mx = __uint_as_float(g_pmax[g * HID + k]);
        acc += m * Wh[k * N_CLASSES + c]
             + s * Wh[(HID + k) * N_CLASSES + c]
             + mx * Wh[(2 * HID + k) * N_CLASSES + c];
    }
    out[g * N_CLASSES + c] = acc;
}

// ---------------- launch ----------------
extern "C" void kernel_launch(void* const* d_in, const int* in_sizes, int n_in,
                              void* d_out, int out_size) {
    const float* x    = (const float*)d_in[0];
    const int*   ei   = (const int*)d_in[1];
    const int*   src  = ei;
    const int*   dst  = ei + N_EDGES;
    const int*   batch = (const int*)d_in[2];
    const float* W1 = (const float*)d_in[3];
    const float* b1 = (const float*)d_in[4];
    const float* g1 = (const float*)d_in[5];
    const float* be1 = (const float*)d_in[6];
    const float* W2 = (const float*)d_in[7];
    const float* b2 = (const float*)d_in[8];
    const float* g2 = (const float*)d_in[9];
    const float* be2 = (const float*)d_in[10];
    const float* W3 = (const float*)d_in[11];
    const float* b3 = (const float*)d_in[12];
    const float* g3 = (const float*)d_in[13];
    const float* be3 = (const float*)d_in[14];
    const float* Wh = (const float*)d_in[15];
    const float* bh = (const float*)d_in[16];
    float* out = (float*)d_out;

    cudaFuncSetAttribute(mma_kernel, cudaFuncAttributeMaxDynamicSharedMemorySize,
                         SMEM_MMA_BYTES);

    // one-time stream/event resources (created on first, non-captured, call)
    static cudaStream_t s1 = nullptr;
    static cudaEvent_t evFork = nullptr, evJoin = nullptr;
    if (s1 == nullptr) {
        cudaStreamCreateWithFlags(&s1, cudaStreamNonBlocking);
        cudaEventCreateWithFlags(&evFork, cudaEventDisableTiming);
        cudaEventCreateWithFlags(&evJoin, cudaEventDisableTiming);
    }

    const int TB = 256;
    const int edgeBlocks = (N_EDGES + TB - 1) / TB;
    const int aggBlocks = (N_NODES + 8 * NPWA - 1) / (8 * NPWA);
    const int poolWarps = (N_NODES + 15) / 16;
    const int poolBlocks = (poolWarps * 32 + TB - 1) / TB;

    zero_cnt_kernel<<<196, TB>>>();
    hist_kernel<<<edgeBlocks, TB>>>(dst);
    scanA_kernel<<<SCAN_NB, 256>>>();

    // fork: mma1 needs only x, W1, g_dinv (ready after scanA); zero_rest is also
    // independent of scanB/scatter — both run on the side stream.
    cudaEventRecord(evFork, 0);
    cudaStreamWaitEvent(s1, evFork, 0);
    zero_rest_kernel<<<128, TB, 0, s1>>>();
    mma_kernel<<<MMA_BLOCKS, 256, SMEM_MMA_BYTES, s1>>>(x, W1, nullptr, nullptr, 0, 0);
    cudaEventRecord(evJoin, s1);

    scanB_kernel<<<1, 512>>>();
    scatter_kernel<<<edgeBlocks, TB>>>(src, dst);

    // join before agg1 (needs g_esrc from scatter, g_hW2 from mma1, g_stats zeroed)
    cudaStreamWaitEvent(0, evJoin, 0);
    agg_kernel<<<aggBlocks, TB>>>(b1, 0);

    // layer 2: A = h1 = relu(bn1(z1)), h1 -> g_h1
    mma_kernel<<<MMA_BLOCKS, 256, SMEM_MMA_BYTES>>>(nullptr, W2, g1, be1, 0, 1);
    agg_kernel<<<aggBlocks, TB>>>(b2, 1);

    // layer 3: A = h2 = relu(bn2(z2) + h1), h2 -> g_h2
    mma_kernel<<<MMA_BLOCKS, 256, SMEM_MMA_BYTES>>>(nullptr, W3, g2, be2, 1, 2);
    agg_kernel<<<aggBlocks, TB>>>(b3, 2);

    // pool (fused bn3 + residual h2) + head
    pool_kernel<<<poolBlocks, TB>>>(batch, g3, be3);
    head_kernel<<<N_GRAPHS, N_CLASSES>>>(Wh, bh, out);
}

// round 17
// speedup vs baseline: 1.2112x; 1.0358x over previous
#include <cuda_runtime.h>
#include <cuda_fp16.h>
#include <cstdint>

#define N_NODES 100000
#define N_EDGES 1600000
#define HID 128
#define NH4 (HID/4)
#define N_GRAPHS 512
#define N_CLASSES 64
#define BN_EPS 1e-5f
#define SCAN_NB 391   // ceil(N_NODES/256)

#define TILE_M 128
#define MMA_BLOCKS ((N_NODES + 2 * TILE_M - 1) / (2 * TILE_M))   // 391 (2 tiles/block)
#define APAD 136                                        // halves per smem row
#define SMEM_MMA_BYTES (2 * 128 * APAD * 2)             // A + B fp16 tiles = 69632
#define NPWA 4                                          // nodes per warp in agg

// ---------------- scratch (device globals; allocation-free) ----------------
__device__ __align__(16) unsigned g_hW2[N_NODES * 64]; // payload = dinv*h@W, half2/u32
__device__ __align__(16) unsigned g_z2 [N_NODES * 64]; // pre-BN conv output, fp16
__device__ __align__(16) unsigned g_h1 [N_NODES * 64]; // h1, fp16
__device__ __align__(16) unsigned g_h2 [N_NODES * 64]; // h2, fp16
__device__ float g_dinv[N_NODES];
__device__ int   g_cnt[N_NODES];
__device__ int   g_rowptr[N_NODES + 1]; // intra-block partial prefix (+ g_boff[i>>8])
__device__ int   g_cursor[N_NODES];
__device__ int   g_bsum[SCAN_NB];
__device__ int   g_boff[SCAN_NB];
__device__ int   g_esrc[N_EDGES];       // CSR-sorted source node per edge
__device__ float g_stats[3 * 2 * HID];
__device__ float g_psum[N_GRAPHS * HID];
__device__ unsigned g_pmax[N_GRAPHS * HID];
__device__ int   g_pcnt[N_GRAPHS];

// ---------------- warp-MMA helpers ----------------
__device__ __forceinline__ uint32_t smem_u32(const void* p) {
    uint32_t a;
    asm("{ .reg .u64 t; cvta.to.shared.u64 t, %1; cvt.u32.u64 %0, t; }" : "=r"(a) : "l"(p));
    return a;
}
__device__ __forceinline__ void ldsm_x4(uint32_t* r, uint32_t addr) {
    asm volatile("ldmatrix.sync.aligned.m8n8.x4.shared.b16 {%0,%1,%2,%3}, [%4];"
                 : "=r"(r[0]), "=r"(r[1]), "=r"(r[2]), "=r"(r[3]) : "r"(addr));
}
__device__ __forceinline__ void ldsm_x4_t(uint32_t* r, uint32_t addr) {
    asm volatile("ldmatrix.sync.aligned.m8n8.x4.trans.shared.b16 {%0,%1,%2,%3}, [%4];"
                 : "=r"(r[0]), "=r"(r[1]), "=r"(r[2]), "=r"(r[3]) : "r"(addr));
}
__device__ __forceinline__ void mma16816(float* c, const uint32_t* a, const uint32_t* b) {
    asm volatile(
        "mma.sync.aligned.m16n8k16.row.col.f32.f16.f16.f32 "
        "{%0,%1,%2,%3}, {%4,%5,%6,%7}, {%8,%9}, {%0,%1,%2,%3};"
        : "+f"(c[0]), "+f"(c[1]), "+f"(c[2]), "+f"(c[3])
        : "r"(a[0]), "r"(a[1]), "r"(a[2]), "r"(a[3]), "r"(b[0]), "r"(b[1]));
}
__device__ __forceinline__ float2 h2f(unsigned u) {
    return __half22float2(*(__half2*)&u);
}
__device__ __forceinline__ __half2 u2h(unsigned u) { return *(__half2*)&u; }

// ---------------- setup kernels ----------------

__global__ __launch_bounds__(256) void zero_cnt_kernel() {
    int i = blockIdx.x * blockDim.x + threadIdx.x;
    int stride = gridDim.x * blockDim.x;
    for (int j = i; j < N_NODES; j += stride) { g_cnt[j] = 0; g_cursor[j] = 0; }
}

__global__ __launch_bounds__(256) void zero_rest_kernel() {
    int i = blockIdx.x * blockDim.x + threadIdx.x;
    int stride = gridDim.x * blockDim.x;
    for (int j = i; j < 3 * 2 * HID; j += stride) g_stats[j] = 0.0f;
    for (int j = i; j < N_GRAPHS * HID; j += stride) { g_psum[j] = 0.0f; g_pmax[j] = 0u; }
    for (int j = i; j < N_GRAPHS; j += stride) g_pcnt[j] = 0;
}

__global__ __launch_bounds__(256) void hist_kernel(const int* __restrict__ dst) {
    int e = blockIdx.x * blockDim.x + threadIdx.x;
    if (e < N_EDGES) atomicAdd(&g_cnt[dst[e]], 1);
}

__global__ __launch_bounds__(256) void scanA_kernel() {
    int t = threadIdx.x, b = blockIdx.x;
    int i = b * 256 + t;
    int v = (i < N_NODES) ? g_cnt[i] : 0;
    if (i < N_NODES) g_dinv[i] = rsqrtf((float)v + 1.0f);
    int x = v;
#pragma unroll
    for (int o = 1; o < 32; o <<= 1) {
        int y = __shfl_up_sync(0xffffffffu, x, o);
        if ((t & 31) >= o) x += y;
    }
    __shared__ int wsum[8];
    if ((t & 31) == 31) wsum[t >> 5] = x;
    __syncthreads();
    if (t < 32) {
        int s = (t < 8) ? wsum[t] : 0;
#pragma unroll
        for (int o = 1; o < 8; o <<= 1) {
            int y = __shfl_up_sync(0xffffffffu, s, o);
            if (t >= o) s += y;
        }
        if (t < 8) wsum[t] = s;
    }
    __syncthreads();
    int warpoff = (t >= 32) ? wsum[(t >> 5) - 1] : 0;
    int incl = x + warpoff;
    if (i < N_NODES) g_rowptr[i] = incl - v;
    if (t == 255) g_bsum[b] = incl;
}

__global__ __launch_bounds__(512) void scanB_kernel() {
    __shared__ int sh[512];
    int t = threadIdx.x;
    int v = (t < SCAN_NB) ? g_bsum[t] : 0;
    sh[t] = v;
    __syncthreads();
    for (int o = 1; o < 512; o <<= 1) {
        int y = (t >= o) ? sh[t - o] : 0;
        __syncthreads();
        sh[t] += y;
        __syncthreads();
    }
    if (t < SCAN_NB) g_boff[t] = sh[t] - v;
    if (t == SCAN_NB - 1) g_rowptr[N_NODES] = v;
}

__global__ __launch_bounds__(256) void scatter_kernel(const int* __restrict__ src,
                                                      const int* __restrict__ dst) {
    int e = blockIdx.x * blockDim.x + threadIdx.x;
    if (e >= N_EDGES) return;
    int d = dst[e];
    int pos = g_rowptr[d] + g_boff[d >> 8] + atomicAdd(&g_cursor[d], 1);
    g_esrc[pos] = src[e];
}

// ---------------- HMMA GEMM: payload = dinv * (A @ W) -> g_hW2 (fp16) ----------------
// Two 128-row tiles per block; B (=W) staged ONCE and reused across both tiles.
// mode 0: A = Aext (x fp32). mode 1: A = relu(bn(g_z2)), h -> g_h1.
// mode 2: A = relu(bn(g_z2) + g_h1), h -> g_h2.
__global__ __launch_bounds__(256) void mma_kernel(const float* __restrict__ Aext,
                                                  const float* __restrict__ W,
                                                  const float* __restrict__ gam,
                                                  const float* __restrict__ bet,
                                                  int statIdx, int mode) {
    extern __shared__ __align__(16) __half smh[];
    __half* As = smh;                  // [128][APAD]
    __half* Bs = smh + 128 * APAD;     // [128][APAD]
    __shared__ __align__(16) float s_sc[HID];
    __shared__ __align__(16) float s_sh[HID];

    int tid = threadIdx.x;
    int lane = tid & 31, wid = tid >> 5;

    if (mode != 0) {
        if (tid < HID) {
            const float* st = &g_stats[statIdx * 2 * HID];
            const float invN = 1.0f / (float)N_NODES;
            float mu = st[tid] * invN;
            float var = st[HID + tid] * invN - mu * mu;
            float scv = gam[tid] * rsqrtf(var + BN_EPS);
            s_sc[tid] = scv;
            s_sh[tid] = bet[tid] - mu * scv;
        }
        __syncthreads();
    }

    // ---- stage B = W once (reused by both tiles) ----
    {
        int r = tid >> 1;
        int hf = (tid & 1) * 64;
#pragma unroll
        for (int cc = 0; cc < 8; ++cc) {
            int c = hf + cc * 8;
            float4 w0 = *(const float4*)&W[r * 128 + c];
            float4 w1 = *(const float4*)&W[r * 128 + c + 4];
            __half2 q0 = __floats2half2_rn(w0.x, w0.y);
            __half2 q1 = __floats2half2_rn(w0.z, w0.w);
            __half2 q2 = __floats2half2_rn(w1.x, w1.y);
            __half2 q3 = __floats2half2_rn(w1.z, w1.w);
            uint4 uw;
            uw.x = *(unsigned*)&q0; uw.y = *(unsigned*)&q1;
            uw.z = *(unsigned*)&q2; uw.w = *(unsigned*)&q3;
            *(uint4*)&Bs[r * APAD + c] = uw;
        }
    }

    uint32_t As_base = smem_u32(As);
    uint32_t Bs_base = smem_u32(Bs);
    int wm = wid & 3;
    int wn = wid >> 2;
    int a_row = wm * 32 + (lane & 7) + ((lane >> 3) & 1) * 8;
    int a_col = (lane >> 4) * 8;
    int b_row = (lane & 7) + ((lane >> 3) & 1) * 8;
    int b_col = wn * 64 + (lane >> 4) * 8;

#pragma unroll 1
    for (int sub = 0; sub < 2; ++sub) {
        int rowBase = blockIdx.x * (2 * TILE_M) + sub * TILE_M;
        if (rowBase >= N_NODES) break;

        // ---- stage A tile (fp16 path with BN fusion) ----
        {
            int r = tid >> 1;
            int hf = (tid & 1) * 64;
            int row = rowBase + r;
            bool valid = row < N_NODES;
            unsigned* hout = (mode == 1) ? g_h1 : g_h2;
#pragma unroll
            for (int cc = 0; cc < 8; ++cc) {
                int c = hf + cc * 8;
                uint4 u = make_uint4(0, 0, 0, 0);
                if (valid) {
                    if (mode == 0) {
                        float4 v0 = *(const float4*)&Aext[row * 128 + c];
                        float4 v1 = *(const float4*)&Aext[row * 128 + c + 4];
                        __half2 p0 = __floats2half2_rn(v0.x, v0.y);
                        __half2 p1 = __floats2half2_rn(v0.z, v0.w);
                        __half2 p2 = __floats2half2_rn(v1.x, v1.y);
                        __half2 p3 = __floats2half2_rn(v1.z, v1.w);
                        u.x = *(unsigned*)&p0; u.y = *(unsigned*)&p1;
                        u.z = *(unsigned*)&p2; u.w = *(unsigned*)&p3;
                    } else {
                        uint4 zu = *(const uint4*)&g_z2[row * 64 + (c >> 1)];
                        float2 f0 = h2f(zu.x), f1 = h2f(zu.y), f2 = h2f(zu.z), f3 = h2f(zu.w);
                        float4 s0 = *(const float4*)&s_sc[c];
                        float4 s1 = *(const float4*)&s_sc[c + 4];
                        float4 h0 = *(const float4*)&s_sh[c];
                        float4 h1 = *(const float4*)&s_sh[c + 4];
                        f0.x = f0.x * s0.x + h0.x; f0.y = f0.y * s0.y + h0.y;
                        f1.x = f1.x * s0.z + h0.z; f1.y = f1.y * s0.w + h0.w;
                        f2.x = f2.x * s1.x + h1.x; f2.y = f2.y * s1.y + h1.y;
                        f3.x = f3.x * s1.z + h1.z; f3.y = f3.y * s1.w + h1.w;
                        if (mode == 2) {
                            uint4 ru = *(const uint4*)&g_h1[row * 64 + (c >> 1)];
                            float2 r0 = h2f(ru.x), r1 = h2f(ru.y), r2 = h2f(ru.z), r3 = h2f(ru.w);
                            f0.x += r0.x; f0.y += r0.y;
                            f1.x += r1.x; f1.y += r1.y;
                            f2.x += r2.x; f2.y += r2.y;
                            f3.x += r3.x; f3.y += r3.y;
                        }
                        f0.x = fmaxf(f0.x, 0.0f); f0.y = fmaxf(f0.y, 0.0f);
                        f1.x = fmaxf(f1.x, 0.0f); f1.y = fmaxf(f1.y, 0.0f);
                        f2.x = fmaxf(f2.x, 0.0f); f2.y = fmaxf(f2.y, 0.0f);
                        f3.x = fmaxf(f3.x, 0.0f); f3.y = fmaxf(f3.y, 0.0f);
                        __half2 p0 = __floats2half2_rn(f0.x, f0.y);
                        __half2 p1 = __floats2half2_rn(f1.x, f1.y);
                        __half2 p2 = __floats2half2_rn(f2.x, f2.y);
                        __half2 p3 = __floats2half2_rn(f3.x, f3.y);
                        u.x = *(unsigned*)&p0; u.y = *(unsigned*)&p1;
                        u.z = *(unsigned*)&p2; u.w = *(unsigned*)&p3;
                        *(uint4*)&hout[row * 64 + (c >> 1)] = u;
                    }
                }
                *(uint4*)&As[r * APAD + c] = u;
            }
        }
        __syncthreads();

        // ---- warp tiles: 4x2 warps, each 32(m) x 64(n) ----
        float acc[2][8][4];
#pragma unroll
        for (int mt = 0; mt < 2; ++mt)
#pragma unroll
            for (int nt = 0; nt < 8; ++nt)
#pragma unroll
                for (int j = 0; j < 4; ++j) acc[mt][nt][j] = 0.0f;

#pragma unroll
        for (int kc = 0; kc < 8; ++kc) {
            int k0 = kc * 16;
            uint32_t afr[2][4];
#pragma unroll
            for (int mt = 0; mt < 2; ++mt) {
                uint32_t addr = As_base + (uint32_t)(((a_row + mt * 16) * APAD) + k0 + a_col) * 2u;
                ldsm_x4(afr[mt], addr);
            }
            uint32_t bfr[8][2];
#pragma unroll
            for (int j = 0; j < 4; ++j) {
                uint32_t r[4];
                uint32_t addr = Bs_base + (uint32_t)(((b_row + k0) * APAD) + b_col + j * 16) * 2u;
                ldsm_x4_t(r, addr);
                bfr[2 * j][0] = r[0]; bfr[2 * j][1] = r[1];
                bfr[2 * j + 1][0] = r[2]; bfr[2 * j + 1][1] = r[3];
            }
#pragma unroll
            for (int mt = 0; mt < 2; ++mt)
#pragma unroll
                for (int nt = 0; nt < 8; ++nt)
                    mma16816(acc[mt][nt], afr[mt], bfr[nt]);
        }
        __syncthreads();   // all LDSM of As done before restaging next tile

        // ---- epilogue: payload = dinv[row] * C, fp16 ----
#pragma unroll
        for (int mt = 0; mt < 2; ++mt) {
            int grow0 = rowBase + wm * 32 + mt * 16 + (lane >> 2);
            float d0 = (grow0 < N_NODES) ? g_dinv[grow0] : 0.0f;
            float d8 = (grow0 + 8 < N_NODES) ? g_dinv[grow0 + 8] : 0.0f;
#pragma unroll
            for (int nt = 0; nt < 8; ++nt) {
                int cidx = wn * 32 + nt * 4 + (lane & 3);
                if (grow0 < N_NODES) {
                    __half2 p = __floats2half2_rn(d0 * acc[mt][nt][0], d0 * acc[mt][nt][1]);
                    g_hW2[grow0 * 64 + cidx] = *(unsigned*)&p;
                }
                if (grow0 + 8 < N_NODES) {
                    __half2 p = __floats2half2_rn(d8 * acc[mt][nt][2], d8 * acc[mt][nt][3]);
                    g_hW2[(grow0 + 8) * 64 + cidx] = *(unsigned*)&p;
                }
            }
        }
    }
}

// ---------------- aggregate (4 nodes/warp, MLP-4 fp16-tree gather) + BN stats ----------------
// z_i = dinv_i * (sum_e payload[src_e] + payload[i]) + b
__global__ __launch_bounds__(256) void agg_kernel(const float* __restrict__ b, int layer) {
    __shared__ float ss[8][HID];
    __shared__ float sq[8][HID];
    int w = (threadIdx.x >> 5);
    int lane = threadIdx.x & 31;
    int node0 = ((blockIdx.x * blockDim.x + threadIdx.x) >> 5) * NPWA;
    const uint2* hw = (const uint2*)g_hW2;
    float4 bb = ((const float4*)b)[lane];
    float4 statS = make_float4(0, 0, 0, 0);
    float4 statQ = make_float4(0, 0, 0, 0);
#pragma unroll 1
    for (int nn = 0; nn < NPWA; ++nn) {
        int node = node0 + nn;
        if (node >= N_NODES) break;
        float4 acc = make_float4(0, 0, 0, 0);
        int e0 = g_rowptr[node] + g_boff[node >> 8];
        int e1 = g_rowptr[node + 1] + g_boff[(node + 1) >> 8];
        int e = e0;
        int efull = e0 + ((e1 - e0) & ~3);
        for (; e < efull; e += 4) {
            int s0 = g_esrc[e];
            int s1 = g_esrc[e + 1];
            int s2 = g_esrc[e + 2];
            int s3 = g_esrc[e + 3];
            uint2 u0 = hw[s0 * 32 + lane];
            uint2 u1 = hw[s1 * 32 + lane];
            uint2 u2 = hw[s2 * 32 + lane];
            uint2 u3 = hw[s3 * 32 + lane];
            __half2 xs = __hadd2(__hadd2(u2h(u0.x), u2h(u1.x)),
                                 __hadd2(u2h(u2.x), u2h(u3.x)));
            __half2 ys = __hadd2(__hadd2(u2h(u0.y), u2h(u1.y)),
                                 __hadd2(u2h(u2.y), u2h(u3.y)));
            float2 fx = __half22float2(xs);
            float2 fy = __half22float2(ys);
            acc.x += fx.x; acc.y += fx.y;
            acc.z += fy.x; acc.w += fy.y;
        }
        for (; e < e1; ++e) {
            int s = g_esrc[e];
            uint2 u = hw[s * 32 + lane];
            float2 f;
            f = h2f(u.x); acc.x += f.x; acc.y += f.y;
            f = h2f(u.y); acc.z += f.x; acc.w += f.y;
        }
        // self term + scale + bias
        {
            uint2 u = hw[node * 32 + lane];
            float2 f0 = h2f(u.x), f1 = h2f(u.y);
            acc.x += f0.x; acc.y += f0.y; acc.z += f1.x; acc.w += f1.y;
        }
        float di = g_dinv[node];
        acc.x = di * acc.x + bb.x;
        acc.y = di * acc.y + bb.y;
        acc.z = di * acc.z + bb.z;
        acc.w = di * acc.w + bb.w;
        __half2 za = __floats2half2_rn(acc.x, acc.y);
        __half2 zb = __floats2half2_rn(acc.z, acc.w);
        uint2 zo;
        zo.x = *(unsigned*)&za; zo.y = *(unsigned*)&zb;
        ((uint2*)g_z2)[node * 32 + lane] = zo;
        statS.x += acc.x; statS.y += acc.y; statS.z += acc.z; statS.w += acc.w;
        statQ.x += acc.x * acc.x; statQ.y += acc.y * acc.y;
        statQ.z += acc.z * acc.z; statQ.w += acc.w * acc.w;
    }
    *(float4*)&ss[w][lane * 4] = statS;
    *(float4*)&sq[w][lane * 4] = statQ;
    __syncthreads();
    int t = threadIdx.x;
    int arr = t >> 7;
    int c = t & 127;
    const float* base = (arr == 0) ? &ss[0][0] : &sq[0][0];
    float total = 0.0f;
#pragma unroll
    for (int ww = 0; ww < 8; ++ww) total += base[ww * HID + c];
    atomicAdd(&g_stats[layer * 2 * HID + arr * HID + c], total);
}

__device__ __forceinline__ void pool_flush(int g, int lane, float4 s, float4 m, int cnt) {
    int base = g * HID + lane * 4;
    atomicAdd(&g_psum[base + 0], s.x);
    atomicAdd(&g_psum[base + 1], s.y);
    atomicAdd(&g_psum[base + 2], s.z);
    atomicAdd(&g_psum[base + 3], s.w);
    atomicMax(&g_pmax[base + 0], __float_as_uint(m.x));
    atomicMax(&g_pmax[base + 1], __float_as_uint(m.y));
    atomicMax(&g_pmax[base + 2], __float_as_uint(m.z));
    atomicMax(&g_pmax[base + 3], __float_as_uint(m.w));
    if (lane == 0) atomicAdd(&g_pcnt[g], cnt);
}

// pool with fused layer-3 BN + residual + relu (BN from g_stats[2]); fp16 inputs
__global__ __launch_bounds__(256) void pool_kernel(const int* __restrict__ batch,
                                                   const float* __restrict__ gam,
                                                   const float* __restrict__ bet) {
    __shared__ __align__(16) float s_sc[HID];
    __shared__ __align__(16) float s_sh[HID];
    {
        int t = threadIdx.x;
        if (t < HID) {
            const float* st = &g_stats[2 * 2 * HID];
            const float invN = 1.0f / (float)N_NODES;
            float mu = st[t] * invN;
            float var = st[HID + t] * invN - mu * mu;
            float scv = gam[t] * rsqrtf(var + BN_EPS);
            s_sc[t] = scv;
            s_sh[t] = bet[t] - mu * scv;
        }
        __syncthreads();
    }
    const int NPW = 16;
    int warp = (blockIdx.x * blockDim.x + threadIdx.x) >> 5;
    int lane = threadIdx.x & 31;
    int n0 = warp * NPW;
    if (n0 >= N_NODES) return;
    int n1 = min(n0 + NPW, N_NODES);
    const uint2* z2 = (const uint2*)g_z2;
    const uint2* r2 = (const uint2*)g_h2;
    float4 sc = *(const float4*)&s_sc[lane * 4];
    float4 sh = *(const float4*)&s_sh[lane * 4];
    float4 sacc = make_float4(0, 0, 0, 0);
    float4 macc = make_float4(0, 0, 0, 0);
    int cur = batch[n0];
    int cnt = 0;
    for (int n = n0; n < n1; ++n) {
        int g = batch[n];
        if (g != cur) {
            pool_flush(cur, lane, sacc, macc, cnt);
            sacc = make_float4(0, 0, 0, 0);
            macc = make_float4(0, 0, 0, 0);
            cnt = 0; cur = g;
        }
        uint2 zu = z2[n * 32 + lane];
        uint2 ru = r2[n * 32 + lane];
        float2 z0 = h2f(zu.x), z1 = h2f(zu.y);
        float2 r0 = h2f(ru.x), r1 = h2f(ru.y);
        float4 v;
        v.x = fmaxf(z0.x * sc.x + sh.x + r0.x, 0.0f);
        v.y = fmaxf(z0.y * sc.y + sh.y + r0.y, 0.0f);
        v.z = fmaxf(z1.x * sc.z + sh.z + r1.x, 0.0f);
        v.w = fmaxf(z1.y * sc.w + sh.w + r1.y, 0.0f);
        sacc.x += v.x; sacc.y += v.y; sacc.z += v.z; sacc.w += v.w;
        macc.x = fmaxf(macc.x, v.x); macc.y = fmaxf(macc.y, v.y);
        macc.z = fmaxf(macc.z, v.z); macc.w = fmaxf(macc.w, v.w);
        ++cnt;
    }
    pool_flush(cur, lane, sacc, macc, cnt);
}

__global__ __launch_bounds__(64) void head_kernel(const float* __restrict__ Wh,
                                                  const float* __restrict__ bh,
                                                  float* __restrict__ out) {
    int g = blockIdx.x;
    int c = threadIdx.x;
    float cntf = (float)g_pcnt[g];
    float inv = 1.0f / fmaxf(cntf, 1.0f);
    float acc = bh[c];
    for (int k = 0; k < HID; ++k) {
        float s = g_psum[g * HID + k];
        float m = s * inv;
        float mx = __uint_as_float(g_pmax[g * HID + k]);
        acc += m * Wh[k * N_CLASSES + c]
             + s * Wh[(HID + k) * N_CLASSES + c]
             + mx * Wh[(2 * HID + k) * N_CLASSES + c];
    }
    out[g * N_CLASSES + c] = acc;
}

// ---------------- launch ----------------
extern "C" void kernel_launch(void* const* d_in, const int* in_sizes, int n_in,
                              void* d_out, int out_size) {
    const float* x    = (const float*)d_in[0];
    const int*   ei   = (const int*)d_in[1];
    const int*   src  = ei;
    const int*   dst  = ei + N_EDGES;
    const int*   batch = (const int*)d_in[2];
    const float* W1 = (const float*)d_in[3];
    const float* b1 = (const float*)d_in[4];
    const float* g1 = (const float*)d_in[5];
    const float* be1 = (const float*)d_in[6];
    const float* W2 = (const float*)d_in[7];
    const float* b2 = (const float*)d_in[8];
    const float* g2 = (const float*)d_in[9];
    const float* be2 = (const float*)d_in[10];
    const float* W3 = (const float*)d_in[11];
    const float* b3 = (const float*)d_in[12];
    const float* g3 = (const float*)d_in[13];
    const float* be3 = (const float*)d_in[14];
    const float* Wh = (const float*)d_in[15];
    const float* bh = (const float*)d_in[16];
    float* out = (float*)d_out;

    cudaFuncSetAttribute(mma_kernel, cudaFuncAttributeMaxDynamicSharedMemorySize,
                         SMEM_MMA_BYTES);

    static cudaStream_t s1 = nullptr;
    static cudaEvent_t evFork = nullptr, evJoin = nullptr;
    if (s1 == nullptr) {
        cudaStreamCreateWithFlags(&s1, cudaStreamNonBlocking);
        cudaEventCreateWithFlags(&evFork, cudaEventDisableTiming);
        cudaEventCreateWithFlags(&evJoin, cudaEventDisableTiming);
    }

    const int TB = 256;
    const int edgeBlocks = (N_EDGES + TB - 1) / TB;
    const int aggBlocks = (N_NODES + 8 * NPWA - 1) / (8 * NPWA);
    const int poolWarps = (N_NODES + 15) / 16;
    const int poolBlocks = (poolWarps * 32 + TB - 1) / TB;

    zero_cnt_kernel<<<196, TB>>>();
    hist_kernel<<<edgeBlocks, TB>>>(dst);
    scanA_kernel<<<SCAN_NB, 256>>>();

    // fork: mma1 needs only x, W1, g_dinv; zero_rest independent of scanB/scatter
    cudaEventRecord(evFork, 0);
    cudaStreamWaitEvent(s1, evFork, 0);
    zero_rest_kernel<<<128, TB, 0, s1>>>();
    mma_kernel<<<MMA_BLOCKS, 256, SMEM_MMA_BYTES, s1>>>(x, W1, nullptr, nullptr, 0, 0);
    cudaEventRecord(evJoin, s1);

    scanB_kernel<<<1, 512>>>();
    scatter_kernel<<<edgeBlocks, TB>>>(src, dst);

    cudaStreamWaitEvent(0, evJoin, 0);
    agg_kernel<<<aggBlocks, TB>>>(b1, 0);

    // layer 2
    mma_kernel<<<MMA_BLOCKS, 256, SMEM_MMA_BYTES>>>(nullptr, W2, g1, be1, 0, 1);
    agg_kernel<<<aggBlocks, TB>>>(b2, 1);

    // layer 3
    mma_kernel<<<MMA_BLOCKS, 256, SMEM_MMA_BYTES>>>(nullptr, W3, g2, be2, 1, 2);
    agg_kernel<<<aggBlocks, TB>>>(b3, 2);

    // pool + head
    pool_kernel<<<poolBlocks, TB>>>(batch, g3, be3);
    head_kernel<<<N_GRAPHS, N_CLASSES>>>(Wh, bh, out);
}